// round 1
// baseline (speedup 1.0000x reference)
#include <cuda_runtime.h>
#include <mma.h>

using namespace nvcuda;

#define BB    2
#define NTOK  2048
#define DIM   128
#define NH    8
#define NW    4
#define DOUT  256
#define BN_   (BB*NTOK)            // 4096
#define FEAT  (NH*DIM)             // 1024
#define SCALE 0.022097086912079608f  // 1/sqrt(2048)

// ---- scratch (sanctioned __device__ globals) ----
__device__ float g_adjsum[(size_t)BB*NTOK*NTOK];          // 33.5 MB
__device__ float g_q[(size_t)NH*BN_*DIM];                  // 16.8 MB
__device__ float g_k[(size_t)NH*BN_*DIM];
__device__ float g_v[(size_t)NH*BN_*DIM];
__device__ float g_S[(size_t)BB*NH*NTOK*NTOK];             // 268 MB
__device__ float g_ocat[(size_t)BN_*FEAT];                 // 16.8 MB

// ============================================================
// K1: adjsum[b,n,m] = sum_w nodeadj[b,n,m,w]
// ============================================================
__global__ void adjsum_kernel(const float4* __restrict__ adj) {
    size_t i = (size_t)blockIdx.x * blockDim.x + threadIdx.x;
    if (i < (size_t)BB*NTOK*NTOK) {
        float4 t = adj[i];
        g_adjsum[i] = (t.x + t.y) + (t.z + t.w);
    }
}

// ============================================================
// K2: q/k/v[h] = X @ W[h] + b[h]   (X: [4096,128], W[h]: [128,128])
// grid: (BN_/64, 3*NH), block 256 (8 warps: 2x4, each 32x32)
// ============================================================
__global__ void qkv_kernel(const float* __restrict__ X,
                           const float* __restrict__ Wq, const float* __restrict__ bq,
                           const float* __restrict__ Wk, const float* __restrict__ bk,
                           const float* __restrict__ Wv, const float* __restrict__ bv) {
    __shared__ __align__(16) float smem[64*128];   // 32 KB
    float* sA = smem;            // 64 x 32
    float* sB = smem + 64*32;    // 32 x 128
    const int tid  = threadIdx.x;
    const int warp = tid >> 5;
    const int wr = warp >> 2, wc = warp & 3;
    const int row0 = blockIdx.x * 64;
    const int z = blockIdx.y;
    const int mat = z >> 3, h = z & 7;

    const float* Wm = (mat == 0 ? Wq : (mat == 1 ? Wk : Wv)) + (size_t)h*DIM*DIM;
    const float* bm = (mat == 0 ? bq : (mat == 1 ? bk : bv)) + (size_t)h*DIM;
    float* outp = (mat == 0 ? g_q : (mat == 1 ? g_k : g_v)) + (size_t)h*BN_*DIM;

    wmma::fragment<wmma::accumulator, 16,16,8, float> acc[2][2];
    #pragma unroll
    for (int i = 0; i < 2; i++)
        #pragma unroll
        for (int j = 0; j < 2; j++) wmma::fill_fragment(acc[i][j], 0.0f);

    for (int kb = 0; kb < DIM; kb += 32) {
        for (int idx = tid; idx < 64*8; idx += 256) {
            int r = idx >> 3, c = idx & 7;
            *(float4*)(sA + r*32 + c*4) =
                *(const float4*)(X + (size_t)(row0 + r)*DIM + kb + c*4);
        }
        for (int idx = tid; idx < 32*32; idx += 256) {
            int r = idx >> 5, c = idx & 31;
            *(float4*)(sB + r*128 + c*4) =
                *(const float4*)(Wm + (size_t)(kb + r)*DIM + c*4);
        }
        __syncthreads();
        #pragma unroll
        for (int kk = 0; kk < 32; kk += 8) {
            wmma::fragment<wmma::matrix_a,16,16,8,wmma::precision::tf32,wmma::row_major> fa[2];
            wmma::fragment<wmma::matrix_b,16,16,8,wmma::precision::tf32,wmma::row_major> fb[2];
            #pragma unroll
            for (int i = 0; i < 2; i++) {
                wmma::load_matrix_sync(fa[i], sA + (wr*32 + i*16)*32 + kk, 32);
                #pragma unroll
                for (int t = 0; t < fa[i].num_elements; t++)
                    fa[i].x[t] = wmma::__float_to_tf32(fa[i].x[t]);
            }
            #pragma unroll
            for (int j = 0; j < 2; j++) {
                wmma::load_matrix_sync(fb[j], sB + kk*128 + wc*32 + j*16, 128);
                #pragma unroll
                for (int t = 0; t < fb[j].num_elements; t++)
                    fb[j].x[t] = wmma::__float_to_tf32(fb[j].x[t]);
            }
            #pragma unroll
            for (int i = 0; i < 2; i++)
                #pragma unroll
                for (int j = 0; j < 2; j++)
                    wmma::mma_sync(acc[i][j], fa[i], fb[j], acc[i][j]);
        }
        __syncthreads();
    }
    float* sO = smem;  // 64 x 128
    #pragma unroll
    for (int i = 0; i < 2; i++)
        #pragma unroll
        for (int j = 0; j < 2; j++)
            wmma::store_matrix_sync(sO + (wr*32 + i*16)*128 + wc*32 + j*16,
                                    acc[i][j], 128, wmma::mem_row_major);
    __syncthreads();
    for (int idx = tid; idx < 64*128; idx += 256) {
        int r = idx >> 7, e = idx & 127;
        outp[(size_t)(row0 + r)*DIM + e] = sO[idx] + bm[e];
    }
}

// ============================================================
// K3: S[b,h] = (Q K^T * SCALE) * adjsum[b]
// grid: (N/64, N/64, B*H), block 128 (4 warps: 2x2, each 32x32)
// ============================================================
__global__ void scores_kernel() {
    __shared__ __align__(16) float smem[64*64];    // 16 KB
    float* sA = smem;           // 64 x 32 (Q)
    float* sB = smem + 2048;    // 64 x 32 (K)
    const int tid  = threadIdx.x;
    const int warp = tid >> 5;
    const int wr = warp >> 1, wc = warp & 1;
    const int n0 = blockIdx.x * 64, m0 = blockIdx.y * 64;
    const int z = blockIdx.z;
    const int b = z >> 3, h = z & 7;
    const float* qp = g_q + (size_t)h*BN_*DIM + (size_t)b*NTOK*DIM;
    const float* kp = g_k + (size_t)h*BN_*DIM + (size_t)b*NTOK*DIM;

    wmma::fragment<wmma::accumulator, 16,16,8, float> acc[2][2];
    #pragma unroll
    for (int i = 0; i < 2; i++)
        #pragma unroll
        for (int j = 0; j < 2; j++) wmma::fill_fragment(acc[i][j], 0.0f);

    for (int kb = 0; kb < DIM; kb += 32) {
        for (int idx = tid; idx < 64*8; idx += 128) {
            int r = idx >> 3, c = idx & 7;
            *(float4*)(sA + r*32 + c*4) =
                *(const float4*)(qp + (size_t)(n0 + r)*DIM + kb + c*4);
            *(float4*)(sB + r*32 + c*4) =
                *(const float4*)(kp + (size_t)(m0 + r)*DIM + kb + c*4);
        }
        __syncthreads();
        #pragma unroll
        for (int kk = 0; kk < 32; kk += 8) {
            wmma::fragment<wmma::matrix_a,16,16,8,wmma::precision::tf32,wmma::row_major> fa[2];
            wmma::fragment<wmma::matrix_b,16,16,8,wmma::precision::tf32,wmma::col_major> fb[2];
            #pragma unroll
            for (int i = 0; i < 2; i++) {
                wmma::load_matrix_sync(fa[i], sA + (wr*32 + i*16)*32 + kk, 32);
                #pragma unroll
                for (int t = 0; t < fa[i].num_elements; t++)
                    fa[i].x[t] = wmma::__float_to_tf32(fa[i].x[t]);
            }
            #pragma unroll
            for (int j = 0; j < 2; j++) {
                wmma::load_matrix_sync(fb[j], sB + (wc*32 + j*16)*32 + kk, 32);
                #pragma unroll
                for (int t = 0; t < fb[j].num_elements; t++)
                    fb[j].x[t] = wmma::__float_to_tf32(fb[j].x[t]);
            }
            #pragma unroll
            for (int i = 0; i < 2; i++)
                #pragma unroll
                for (int j = 0; j < 2; j++)
                    wmma::mma_sync(acc[i][j], fa[i], fb[j], acc[i][j]);
        }
        __syncthreads();
    }
    float* sO = smem;  // 64 x 64
    #pragma unroll
    for (int i = 0; i < 2; i++)
        #pragma unroll
        for (int j = 0; j < 2; j++)
            wmma::store_matrix_sync(sO + (wr*32 + i*16)*64 + wc*32 + j*16,
                                    acc[i][j], 64, wmma::mem_row_major);
    __syncthreads();
    const float* adjp = g_adjsum + (size_t)b*NTOK*NTOK;
    float* Sp = g_S + (size_t)(b*NH + h)*NTOK*NTOK;
    for (int idx = tid; idx < 64*64; idx += 128) {
        int r = idx >> 6, c = idx & 63;
        int n = n0 + r, m = m0 + c;
        Sp[(size_t)n*NTOK + m] = sO[idx] * SCALE * adjp[(size_t)n*NTOK + m];
    }
}

// ============================================================
// K4: in-place row softmax over last axis (2048)
// grid: B*H*N blocks, 256 threads, 8 elems/thread
// ============================================================
__global__ void softmax_kernel() {
    __shared__ float red[256];
    const size_t row = blockIdx.x;
    float* p = g_S + row * NTOK;
    const int tid = threadIdx.x;
    float4 v0 = ((float4*)p)[tid];
    float4 v1 = ((float4*)p)[tid + 256];

    float m = fmaxf(fmaxf(fmaxf(v0.x, v0.y), fmaxf(v0.z, v0.w)),
                    fmaxf(fmaxf(v1.x, v1.y), fmaxf(v1.z, v1.w)));
    red[tid] = m; __syncthreads();
    #pragma unroll
    for (int s = 128; s > 0; s >>= 1) {
        if (tid < s) red[tid] = fmaxf(red[tid], red[tid + s]);
        __syncthreads();
    }
    const float rmax = red[0];
    __syncthreads();

    v0.x = __expf(v0.x - rmax); v0.y = __expf(v0.y - rmax);
    v0.z = __expf(v0.z - rmax); v0.w = __expf(v0.w - rmax);
    v1.x = __expf(v1.x - rmax); v1.y = __expf(v1.y - rmax);
    v1.z = __expf(v1.z - rmax); v1.w = __expf(v1.w - rmax);
    float s8 = ((v0.x + v0.y) + (v0.z + v0.w)) + ((v1.x + v1.y) + (v1.z + v1.w));
    red[tid] = s8; __syncthreads();
    #pragma unroll
    for (int s = 128; s > 0; s >>= 1) {
        if (tid < s) red[tid] += red[tid + s];
        __syncthreads();
    }
    const float inv = 1.0f / red[0];

    v0.x *= inv; v0.y *= inv; v0.z *= inv; v0.w *= inv;
    v1.x *= inv; v1.y *= inv; v1.z *= inv; v1.w *= inv;
    ((float4*)p)[tid]       = v0;
    ((float4*)p)[tid + 256] = v1;
}

// ============================================================
// K5: O[b,h] = attn[b,h] @ V[b,h]  -> g_ocat[bn, h*128+e]
// grid: (N/64, B*H), block 256 (8 warps: 2x4, each 32x32)
// ============================================================
__global__ void av_kernel() {
    __shared__ __align__(16) float smem[64*128];   // 32 KB
    float* sA = smem;           // 64 x 32 (attn)
    float* sB = smem + 2048;    // 32 x 128 (V)
    const int tid  = threadIdx.x;
    const int warp = tid >> 5;
    const int wr = warp >> 2, wc = warp & 3;
    const int n0 = blockIdx.x * 64;
    const int z = blockIdx.y;
    const int b = z >> 3, h = z & 7;
    const float* Sp = g_S + (size_t)(b*NH + h)*NTOK*NTOK;
    const float* vp = g_v + (size_t)h*BN_*DIM + (size_t)b*NTOK*DIM;

    wmma::fragment<wmma::accumulator, 16,16,8, float> acc[2][2];
    #pragma unroll
    for (int i = 0; i < 2; i++)
        #pragma unroll
        for (int j = 0; j < 2; j++) wmma::fill_fragment(acc[i][j], 0.0f);

    for (int kb = 0; kb < NTOK; kb += 32) {
        for (int idx = tid; idx < 64*8; idx += 256) {
            int r = idx >> 3, c = idx & 7;
            *(float4*)(sA + r*32 + c*4) =
                *(const float4*)(Sp + (size_t)(n0 + r)*NTOK + kb + c*4);
        }
        for (int idx = tid; idx < 32*32; idx += 256) {
            int r = idx >> 5, c = idx & 31;
            *(float4*)(sB + r*128 + c*4) =
                *(const float4*)(vp + (size_t)(kb + r)*DIM + c*4);
        }
        __syncthreads();
        #pragma unroll
        for (int kk = 0; kk < 32; kk += 8) {
            wmma::fragment<wmma::matrix_a,16,16,8,wmma::precision::tf32,wmma::row_major> fa[2];
            wmma::fragment<wmma::matrix_b,16,16,8,wmma::precision::tf32,wmma::row_major> fb[2];
            #pragma unroll
            for (int i = 0; i < 2; i++) {
                wmma::load_matrix_sync(fa[i], sA + (wr*32 + i*16)*32 + kk, 32);
                #pragma unroll
                for (int t = 0; t < fa[i].num_elements; t++)
                    fa[i].x[t] = wmma::__float_to_tf32(fa[i].x[t]);
            }
            #pragma unroll
            for (int j = 0; j < 2; j++) {
                wmma::load_matrix_sync(fb[j], sB + kk*128 + wc*32 + j*16, 128);
                #pragma unroll
                for (int t = 0; t < fb[j].num_elements; t++)
                    fb[j].x[t] = wmma::__float_to_tf32(fb[j].x[t]);
            }
            #pragma unroll
            for (int i = 0; i < 2; i++)
                #pragma unroll
                for (int j = 0; j < 2; j++)
                    wmma::mma_sync(acc[i][j], fa[i], fb[j], acc[i][j]);
        }
        __syncthreads();
    }
    float* sO = smem;  // 64 x 128
    #pragma unroll
    for (int i = 0; i < 2; i++)
        #pragma unroll
        for (int j = 0; j < 2; j++)
            wmma::store_matrix_sync(sO + (wr*32 + i*16)*128 + wc*32 + j*16,
                                    acc[i][j], 128, wmma::mem_row_major);
    __syncthreads();
    for (int idx = tid; idx < 64*128; idx += 256) {
        int r = idx >> 7, e = idx & 127;
        g_ocat[(size_t)(b*NTOK + n0 + r)*FEAT + h*DIM + e] = sO[idx];
    }
}

// ============================================================
// K6: out = ocat[4096,1024] @ Wout[1024,256] + bout
// grid: (BN_/64, DOUT/64), block 128 (4 warps: 2x2, each 32x32)
// ============================================================
__global__ void outproj_kernel(const float* __restrict__ Wout,
                               const float* __restrict__ bout,
                               float* __restrict__ out) {
    __shared__ __align__(16) float smem[64*64];    // 16 KB
    float* sA = smem;           // 64 x 32
    float* sB = smem + 2048;    // 32 x 64
    const int tid  = threadIdx.x;
    const int warp = tid >> 5;
    const int wr = warp >> 1, wc = warp & 1;
    const int r0 = blockIdx.x * 64, c0 = blockIdx.y * 64;

    wmma::fragment<wmma::accumulator, 16,16,8, float> acc[2][2];
    #pragma unroll
    for (int i = 0; i < 2; i++)
        #pragma unroll
        for (int j = 0; j < 2; j++) wmma::fill_fragment(acc[i][j], 0.0f);

    for (int kb = 0; kb < FEAT; kb += 32) {
        for (int idx = tid; idx < 64*8; idx += 128) {
            int r = idx >> 3, c = idx & 7;
            *(float4*)(sA + r*32 + c*4) =
                *(const float4*)(g_ocat + (size_t)(r0 + r)*FEAT + kb + c*4);
        }
        for (int idx = tid; idx < 32*16; idx += 128) {
            int r = idx >> 4, c = idx & 15;
            *(float4*)(sB + r*64 + c*4) =
                *(const float4*)(Wout + (size_t)(kb + r)*DOUT + c0 + c*4);
        }
        __syncthreads();
        #pragma unroll
        for (int kk = 0; kk < 32; kk += 8) {
            wmma::fragment<wmma::matrix_a,16,16,8,wmma::precision::tf32,wmma::row_major> fa[2];
            wmma::fragment<wmma::matrix_b,16,16,8,wmma::precision::tf32,wmma::row_major> fb[2];
            #pragma unroll
            for (int i = 0; i < 2; i++) {
                wmma::load_matrix_sync(fa[i], sA + (wr*32 + i*16)*32 + kk, 32);
                #pragma unroll
                for (int t = 0; t < fa[i].num_elements; t++)
                    fa[i].x[t] = wmma::__float_to_tf32(fa[i].x[t]);
            }
            #pragma unroll
            for (int j = 0; j < 2; j++) {
                wmma::load_matrix_sync(fb[j], sB + kk*64 + wc*32 + j*16, 64);
                #pragma unroll
                for (int t = 0; t < fb[j].num_elements; t++)
                    fb[j].x[t] = wmma::__float_to_tf32(fb[j].x[t]);
            }
            #pragma unroll
            for (int i = 0; i < 2; i++)
                #pragma unroll
                for (int j = 0; j < 2; j++)
                    wmma::mma_sync(acc[i][j], fa[i], fb[j], acc[i][j]);
        }
        __syncthreads();
    }
    float* sO = smem;  // 64 x 64
    #pragma unroll
    for (int i = 0; i < 2; i++)
        #pragma unroll
        for (int j = 0; j < 2; j++)
            wmma::store_matrix_sync(sO + (wr*32 + i*16)*64 + wc*32 + j*16,
                                    acc[i][j], 64, wmma::mem_row_major);
    __syncthreads();
    for (int idx = tid; idx < 64*64; idx += 128) {
        int r = idx >> 6, c = idx & 63;
        out[(size_t)(r0 + r)*DOUT + c0 + c] = sO[idx] + bout[c0 + c];
    }
}

// ============================================================
extern "C" void kernel_launch(void* const* d_in, const int* in_sizes, int n_in,
                              void* d_out, int out_size) {
    const float* X    = (const float*)d_in[0];
    const float* adj  = (const float*)d_in[1];
    const float* Wq   = (const float*)d_in[2];
    const float* bq   = (const float*)d_in[3];
    const float* Wk   = (const float*)d_in[4];
    const float* bk   = (const float*)d_in[5];
    const float* Wv   = (const float*)d_in[6];
    const float* bv   = (const float*)d_in[7];
    const float* Wout = (const float*)d_in[8];
    const float* bout = (const float*)d_in[9];
    float* out = (float*)d_out;

    // K1: adjacency reduce
    {
        size_t total = (size_t)BB*NTOK*NTOK;
        adjsum_kernel<<<(unsigned)((total + 255) / 256), 256>>>((const float4*)adj);
    }
    // K2: QKV projections
    qkv_kernel<<<dim3(BN_/64, 3*NH), 256>>>(X, Wq, bq, Wk, bk, Wv, bv);
    // K3: scores
    scores_kernel<<<dim3(NTOK/64, NTOK/64, BB*NH), 128>>>();
    // K4: softmax
    softmax_kernel<<<BB*NH*NTOK, 256>>>();
    // K5: attn @ V
    av_kernel<<<dim3(NTOK/64, BB*NH), 256>>>();
    // K6: output projection
    outproj_kernel<<<dim3(BN_/64, DOUT/64), 128>>>(Wout, bout, out);
}

// round 2
// speedup vs baseline: 1.5723x; 1.5723x over previous
#include <cuda_runtime.h>
#include <mma.h>

using namespace nvcuda;

#define BB    2
#define NTOK  2048
#define DIM   128
#define NH    8
#define DOUT  256
#define BN_   (BB*NTOK)            // 4096
#define FEAT  (NH*DIM)             // 1024
#define SCALE 0.022097086912079608f  // 1/sqrt(2048)
#define LDS_  132                  // padded leading dim for 128-wide f32 tiles

// ---- scratch (sanctioned __device__ globals) ----
__device__ float g_adjsum[(size_t)BB*NTOK*NTOK];          // 33.5 MB
__device__ float g_q[(size_t)NH*BN_*DIM];                  // 16.8 MB
__device__ float g_k[(size_t)NH*BN_*DIM];
__device__ float g_v[(size_t)NH*BN_*DIM];
__device__ float g_ocat[(size_t)BN_*FEAT];                 // 16.8 MB

// ============================================================
// K1: adjsum[b,n,m] = sum_w nodeadj[b,n,m,w]
// ============================================================
__global__ void adjsum_kernel(const float4* __restrict__ adj) {
    size_t i = (size_t)blockIdx.x * blockDim.x + threadIdx.x;
    if (i < (size_t)BB*NTOK*NTOK) {
        float4 t = adj[i];
        g_adjsum[i] = (t.x + t.y) + (t.z + t.w);
    }
}

// ============================================================
// K2: q/k/v[h] = X @ W[h] + b[h]   (X: [4096,128], W[h]: [128,128])
// grid: (BN_/64, 3*NH), block 256 (8 warps: 2x4, each 32x32)
// ============================================================
__global__ void qkv_kernel(const float* __restrict__ X,
                           const float* __restrict__ Wq, const float* __restrict__ bq,
                           const float* __restrict__ Wk, const float* __restrict__ bk,
                           const float* __restrict__ Wv, const float* __restrict__ bv) {
    __shared__ __align__(16) float smem[64*128];   // 32 KB
    float* sA = smem;            // 64 x 32
    float* sB = smem + 64*32;    // 32 x 128
    const int tid  = threadIdx.x;
    const int warp = tid >> 5;
    const int wr = warp >> 2, wc = warp & 3;
    const int row0 = blockIdx.x * 64;
    const int z = blockIdx.y;
    const int mat = z >> 3, h = z & 7;

    const float* Wm = (mat == 0 ? Wq : (mat == 1 ? Wk : Wv)) + (size_t)h*DIM*DIM;
    const float* bm = (mat == 0 ? bq : (mat == 1 ? bk : bv)) + (size_t)h*DIM;
    float* outp = (mat == 0 ? g_q : (mat == 1 ? g_k : g_v)) + (size_t)h*BN_*DIM;

    wmma::fragment<wmma::accumulator, 16,16,8, float> acc[2][2];
    #pragma unroll
    for (int i = 0; i < 2; i++)
        #pragma unroll
        for (int j = 0; j < 2; j++) wmma::fill_fragment(acc[i][j], 0.0f);

    for (int kb = 0; kb < DIM; kb += 32) {
        for (int idx = tid; idx < 64*8; idx += 256) {
            int r = idx >> 3, c = idx & 7;
            float4 t = *(const float4*)(X + (size_t)(row0 + r)*DIM + kb + c*4);
            float* d = sA + r*32 + c*4;
            d[0] = wmma::__float_to_tf32(t.x); d[1] = wmma::__float_to_tf32(t.y);
            d[2] = wmma::__float_to_tf32(t.z); d[3] = wmma::__float_to_tf32(t.w);
        }
        for (int idx = tid; idx < 32*32; idx += 256) {
            int r = idx >> 5, c = idx & 31;
            float4 t = *(const float4*)(Wm + (size_t)(kb + r)*DIM + c*4);
            float* d = sB + r*128 + c*4;
            d[0] = wmma::__float_to_tf32(t.x); d[1] = wmma::__float_to_tf32(t.y);
            d[2] = wmma::__float_to_tf32(t.z); d[3] = wmma::__float_to_tf32(t.w);
        }
        __syncthreads();
        #pragma unroll
        for (int kk = 0; kk < 32; kk += 8) {
            wmma::fragment<wmma::matrix_a,16,16,8,wmma::precision::tf32,wmma::row_major> fa[2];
            wmma::fragment<wmma::matrix_b,16,16,8,wmma::precision::tf32,wmma::row_major> fb[2];
            #pragma unroll
            for (int i = 0; i < 2; i++)
                wmma::load_matrix_sync(fa[i], sA + (wr*32 + i*16)*32 + kk, 32);
            #pragma unroll
            for (int j = 0; j < 2; j++)
                wmma::load_matrix_sync(fb[j], sB + kk*128 + wc*32 + j*16, 128);
            #pragma unroll
            for (int i = 0; i < 2; i++)
                #pragma unroll
                for (int j = 0; j < 2; j++)
                    wmma::mma_sync(acc[i][j], fa[i], fb[j], acc[i][j]);
        }
        __syncthreads();
    }
    float* sO = smem;  // 64 x 128
    #pragma unroll
    for (int i = 0; i < 2; i++)
        #pragma unroll
        for (int j = 0; j < 2; j++)
            wmma::store_matrix_sync(sO + (wr*32 + i*16)*128 + wc*32 + j*16,
                                    acc[i][j], 128, wmma::mem_row_major);
    __syncthreads();
    for (int idx = tid; idx < 64*128; idx += 256) {
        int r = idx >> 7, e = idx & 127;
        outp[(size_t)(row0 + r)*DIM + e] = sO[idx] + bm[e];
    }
}

// ============================================================
// K3 (FUSED): per (b,h,128-row tile):
//   S = (Q K^T)                       (wmma tf32, Q in registers)
//   P = exp(S * SCALE * adjsum)       (no max: |scores| << 1, overflow-safe)
//   O += P @ V  (register acc), l += rowsum(P)
//   out row = O / l  -> g_ocat (head-concatenated)
// grid: (NTOK/128, B*H), block 256 (8 warps, each 16 rows x 128 cols)
// ============================================================
__global__ __launch_bounds__(256, 1) void fused_attn_kernel() {
    extern __shared__ __align__(16) float dsm[];
    float* sS = dsm;                 // 128 x LDS_  (Q staging, then S/P tile)
    float* sK = dsm + 128*LDS_;      // 128 x LDS_  (K tile)
    float* sV = sK  + 128*LDS_;      // 128 x LDS_  (V tile)
    __shared__ float sL[128][2];     // row-sum accumulators

    const int tid  = threadIdx.x;
    const int warp = tid >> 5;
    const int n0 = blockIdx.x * 128;
    const int b = blockIdx.y >> 3, h = blockIdx.y & 7;

    const float* qp   = g_q + (size_t)h*BN_*DIM + (size_t)b*NTOK*DIM;
    const float* kp   = g_k + (size_t)h*BN_*DIM + (size_t)b*NTOK*DIM;
    const float* vp   = g_v + (size_t)h*BN_*DIM + (size_t)b*NTOK*DIM;
    const float* adjp = g_adjsum + (size_t)b*NTOK*NTOK;

    // ---- stage Q tile (tf32-rounded) into sS ----
    for (int idx = tid; idx < 128*32; idx += 256) {
        int r = idx >> 5, c4 = idx & 31;
        float4 t = *(const float4*)(qp + (size_t)(n0 + r)*DIM + c4*4);
        float* d = sS + r*LDS_ + c4*4;
        d[0] = wmma::__float_to_tf32(t.x); d[1] = wmma::__float_to_tf32(t.y);
        d[2] = wmma::__float_to_tf32(t.z); d[3] = wmma::__float_to_tf32(t.w);
    }
    if (tid < 128) { sL[tid][0] = 0.f; sL[tid][1] = 0.f; }
    __syncthreads();

    // ---- Q fragments into registers (warp owns rows warp*16..warp*16+15) ----
    wmma::fragment<wmma::matrix_a,16,16,8,wmma::precision::tf32,wmma::row_major> aQ[16];
    #pragma unroll
    for (int k = 0; k < 16; k++)
        wmma::load_matrix_sync(aQ[k], sS + (warp*16)*LDS_ + k*8, LDS_);

    wmma::fragment<wmma::accumulator,16,16,8,float> oacc[8];
    #pragma unroll
    for (int j = 0; j < 8; j++) wmma::fill_fragment(oacc[j], 0.0f);
    __syncthreads();   // all warps done reading Q from sS before it becomes S

    for (int it = 0; it < 16; it++) {
        const int m0 = it * 128;
        // ---- load K,V tiles (tf32-rounded) ----
        for (int idx = tid; idx < 128*32; idx += 256) {
            int r = idx >> 5, c4 = idx & 31;
            float4 tk = *(const float4*)(kp + (size_t)(m0 + r)*DIM + c4*4);
            float4 tv = *(const float4*)(vp + (size_t)(m0 + r)*DIM + c4*4);
            float* dk = sK + r*LDS_ + c4*4;
            float* dv = sV + r*LDS_ + c4*4;
            dk[0] = wmma::__float_to_tf32(tk.x); dk[1] = wmma::__float_to_tf32(tk.y);
            dk[2] = wmma::__float_to_tf32(tk.z); dk[3] = wmma::__float_to_tf32(tk.w);
            dv[0] = wmma::__float_to_tf32(tv.x); dv[1] = wmma::__float_to_tf32(tv.y);
            dv[2] = wmma::__float_to_tf32(tv.z); dv[3] = wmma::__float_to_tf32(tv.w);
        }
        __syncthreads();

        // ---- S = Q K^T (warp: 16 x 128 strip) ----
        {
            wmma::fragment<wmma::accumulator,16,16,8,float> sacc[8];
            #pragma unroll
            for (int j = 0; j < 8; j++) wmma::fill_fragment(sacc[j], 0.0f);
            #pragma unroll
            for (int k = 0; k < 16; k++) {
                #pragma unroll
                for (int j = 0; j < 8; j++) {
                    wmma::fragment<wmma::matrix_b,16,16,8,wmma::precision::tf32,wmma::col_major> bK;
                    wmma::load_matrix_sync(bK, sK + (j*16)*LDS_ + k*8, LDS_);
                    wmma::mma_sync(sacc[j], aQ[k], bK, sacc[j]);
                }
            }
            #pragma unroll
            for (int j = 0; j < 8; j++)
                wmma::store_matrix_sync(sS + (warp*16)*LDS_ + j*16, sacc[j],
                                        LDS_, wmma::mem_row_major);
        }
        __syncthreads();

        // ---- P = exp(S*SCALE*adj), accumulate row sums ----
        {
            const int r = tid >> 1, half = tid & 1;
            const float* arow = adjp + (size_t)(n0 + r)*NTOK + m0 + half*64;
            float* srow = sS + r*LDS_ + half*64;
            float lsum = 0.f;
            #pragma unroll
            for (int c = 0; c < 64; c += 4) {
                float4 a4 = *(const float4*)(arow + c);
                float e0 = __expf(srow[c+0] * SCALE * a4.x);
                float e1 = __expf(srow[c+1] * SCALE * a4.y);
                float e2 = __expf(srow[c+2] * SCALE * a4.z);
                float e3 = __expf(srow[c+3] * SCALE * a4.w);
                lsum += (e0 + e1) + (e2 + e3);
                srow[c+0] = wmma::__float_to_tf32(e0);
                srow[c+1] = wmma::__float_to_tf32(e1);
                srow[c+2] = wmma::__float_to_tf32(e2);
                srow[c+3] = wmma::__float_to_tf32(e3);
            }
            sL[r][half] += lsum;
        }
        __syncthreads();

        // ---- O += P @ V ----
        #pragma unroll
        for (int k = 0; k < 16; k++) {
            wmma::fragment<wmma::matrix_a,16,16,8,wmma::precision::tf32,wmma::row_major> aP;
            wmma::load_matrix_sync(aP, sS + (warp*16)*LDS_ + k*8, LDS_);
            #pragma unroll
            for (int j = 0; j < 8; j++) {
                wmma::fragment<wmma::matrix_b,16,16,8,wmma::precision::tf32,wmma::row_major> bV;
                wmma::load_matrix_sync(bV, sV + (k*8)*LDS_ + j*16, LDS_);
                wmma::mma_sync(oacc[j], aP, bV, oacc[j]);
            }
        }
        __syncthreads();   // before next iteration overwrites sK/sV/sS
    }

    // ---- epilogue: O / l -> g_ocat ----
    #pragma unroll
    for (int j = 0; j < 8; j++)
        wmma::store_matrix_sync(sS + (warp*16)*LDS_ + j*16, oacc[j],
                                LDS_, wmma::mem_row_major);
    __syncthreads();
    for (int idx = tid; idx < 128*128; idx += 256) {
        int r = idx >> 7, c = idx & 127;
        float l = sL[r][0] + sL[r][1];
        g_ocat[(size_t)(b*NTOK + n0 + r)*FEAT + h*DIM + c] = sS[r*LDS_ + c] / l;
    }
}

// ============================================================
// K6: out = ocat[4096,1024] @ Wout[1024,256] + bout
// grid: (BN_/64, DOUT/64), block 128 (4 warps: 2x2, each 32x32)
// ============================================================
__global__ void outproj_kernel(const float* __restrict__ Wout,
                               const float* __restrict__ bout,
                               float* __restrict__ out) {
    __shared__ __align__(16) float smem[64*64];    // 16 KB
    float* sA = smem;           // 64 x 32
    float* sB = smem + 2048;    // 32 x 64
    const int tid  = threadIdx.x;
    const int warp = tid >> 5;
    const int wr = warp >> 1, wc = warp & 1;
    const int r0 = blockIdx.x * 64, c0 = blockIdx.y * 64;

    wmma::fragment<wmma::accumulator, 16,16,8, float> acc[2][2];
    #pragma unroll
    for (int i = 0; i < 2; i++)
        #pragma unroll
        for (int j = 0; j < 2; j++) wmma::fill_fragment(acc[i][j], 0.0f);

    for (int kb = 0; kb < FEAT; kb += 32) {
        for (int idx = tid; idx < 64*8; idx += 128) {
            int r = idx >> 3, c = idx & 7;
            float4 t = *(const float4*)(g_ocat + (size_t)(r0 + r)*FEAT + kb + c*4);
            float* d = sA + r*32 + c*4;
            d[0] = wmma::__float_to_tf32(t.x); d[1] = wmma::__float_to_tf32(t.y);
            d[2] = wmma::__float_to_tf32(t.z); d[3] = wmma::__float_to_tf32(t.w);
        }
        for (int idx = tid; idx < 32*16; idx += 128) {
            int r = idx >> 4, c = idx & 15;
            float4 t = *(const float4*)(Wout + (size_t)(kb + r)*DOUT + c0 + c*4);
            float* d = sB + r*64 + c*4;
            d[0] = wmma::__float_to_tf32(t.x); d[1] = wmma::__float_to_tf32(t.y);
            d[2] = wmma::__float_to_tf32(t.z); d[3] = wmma::__float_to_tf32(t.w);
        }
        __syncthreads();
        #pragma unroll
        for (int kk = 0; kk < 32; kk += 8) {
            wmma::fragment<wmma::matrix_a,16,16,8,wmma::precision::tf32,wmma::row_major> fa[2];
            wmma::fragment<wmma::matrix_b,16,16,8,wmma::precision::tf32,wmma::row_major> fb[2];
            #pragma unroll
            for (int i = 0; i < 2; i++)
                wmma::load_matrix_sync(fa[i], sA + (wr*32 + i*16)*32 + kk, 32);
            #pragma unroll
            for (int j = 0; j < 2; j++)
                wmma::load_matrix_sync(fb[j], sB + kk*64 + wc*32 + j*16, 64);
            #pragma unroll
            for (int i = 0; i < 2; i++)
                #pragma unroll
                for (int j = 0; j < 2; j++)
                    wmma::mma_sync(acc[i][j], fa[i], fb[j], acc[i][j]);
        }
        __syncthreads();
    }
    float* sO = smem;  // 64 x 64
    #pragma unroll
    for (int i = 0; i < 2; i++)
        #pragma unroll
        for (int j = 0; j < 2; j++)
            wmma::store_matrix_sync(sO + (wr*32 + i*16)*64 + wc*32 + j*16,
                                    acc[i][j], 64, wmma::mem_row_major);
    __syncthreads();
    for (int idx = tid; idx < 64*64; idx += 128) {
        int r = idx >> 6, c = idx & 63;
        out[(size_t)(r0 + r)*DOUT + c0 + c] = sO[idx] + bout[c0 + c];
    }
}

// ============================================================
extern "C" void kernel_launch(void* const* d_in, const int* in_sizes, int n_in,
                              void* d_out, int out_size) {
    const float* X    = (const float*)d_in[0];
    const float* adj  = (const float*)d_in[1];
    const float* Wq   = (const float*)d_in[2];
    const float* bq   = (const float*)d_in[3];
    const float* Wk   = (const float*)d_in[4];
    const float* bk   = (const float*)d_in[5];
    const float* Wv   = (const float*)d_in[6];
    const float* bv   = (const float*)d_in[7];
    const float* Wout = (const float*)d_in[8];
    const float* bout = (const float*)d_in[9];
    float* out = (float*)d_out;

    const int fused_smem = 3 * 128 * LDS_ * sizeof(float);  // 202,752 B
    cudaFuncSetAttribute(fused_attn_kernel,
                         cudaFuncAttributeMaxDynamicSharedMemorySize, fused_smem);

    // K1: adjacency reduce
    {
        size_t total = (size_t)BB*NTOK*NTOK;
        adjsum_kernel<<<(unsigned)((total + 255) / 256), 256>>>((const float4*)adj);
    }
    // K2: QKV projections
    qkv_kernel<<<dim3(BN_/64, 3*NH), 256>>>(X, Wq, bq, Wk, bk, Wv, bv);
    // K3: fused scores + softmax + attn@V
    fused_attn_kernel<<<dim3(NTOK/128, BB*NH), 256, fused_smem>>>();
    // K6: output projection
    outproj_kernel<<<dim3(BN_/64, DOUT/64), 128>>>(Wout, bout, out);
}

// round 4
// speedup vs baseline: 4.5418x; 2.8887x over previous
#include <cuda_runtime.h>
#include <cuda_fp16.h>
#include <mma.h>
#include <cstdint>

using namespace nvcuda;

#define BB    2
#define NTOK  2048
#define DIM   128
#define NH    8
#define DOUT  256
#define BN_   (BB*NTOK)            // 4096
#define FEAT  (NH*DIM)             // 1024
#define SCALE 0.022097086912079608f  // 1/sqrt(2048)
#define LDH   136                  // fp16 tile leading dim (mult of 8)
#define LDS4  132                  // fp32 S-tile leading dim (mult of 4)

// ---- scratch (sanctioned __device__ globals) ----
__device__ float g_adjsum[(size_t)BB*NTOK*NTOK];                    // 33.5 MB
__device__ __align__(16) __half g_q[(size_t)NH*BN_*DIM];            // 8.4 MB
__device__ __align__(16) __half g_k[(size_t)NH*BN_*DIM];
__device__ __align__(16) __half g_v[(size_t)NH*BN_*DIM];
__device__ __align__(16) __half g_ocat[(size_t)BN_*FEAT];           // 8.4 MB
__device__ float g_psum[4][(size_t)BN_*DOUT];                       // 16.8 MB

// ============================================================
// K1: adjsum[b,n,m] = sum_w nodeadj[b,n,m,w]
// ============================================================
__global__ void adjsum_kernel(const float4* __restrict__ adj) {
    size_t i = (size_t)blockIdx.x * blockDim.x + threadIdx.x;
    if (i < (size_t)BB*NTOK*NTOK) {
        float4 t = adj[i];
        g_adjsum[i] = (t.x + t.y) + (t.z + t.w);
    }
}

// ============================================================
// K2: q/k/v[h] = fp16( X @ W[h] + b[h] )
// grid (BN_/64, 3*NH), block 256 (8 warps: 2x4, each 32x32)
// ============================================================
__global__ void qkv_kernel(const float* __restrict__ X,
                           const float* __restrict__ Wq, const float* __restrict__ bq,
                           const float* __restrict__ Wk, const float* __restrict__ bk,
                           const float* __restrict__ Wv, const float* __restrict__ bv) {
    __shared__ __align__(16) char smem_raw[17408 + 34816];   // sA 64x136 h | sB 128x136 h
    __half* sA = (__half*)smem_raw;
    __half* sB = (__half*)(smem_raw + 17408);
    float*  sO = (float*)(smem_raw + 17408);    // alias sB after MMA (64x132 f32)
    const int tid  = threadIdx.x;
    const int warp = tid >> 5;
    const int wr = warp >> 2, wc = warp & 3;
    const int row0 = blockIdx.x * 64;
    const int z = blockIdx.y;
    const int mat = z >> 3, h = z & 7;

    const float* Wm = (mat == 0 ? Wq : (mat == 1 ? Wk : Wv)) + (size_t)h*DIM*DIM;
    const float* bm = (mat == 0 ? bq : (mat == 1 ? bk : bv)) + (size_t)h*DIM;
    __half* outp = (mat == 0 ? g_q : (mat == 1 ? g_k : g_v)) + (size_t)h*BN_*DIM;

    // stage X tile (fp32 -> fp16)
    for (int idx = tid; idx < 64*32; idx += 256) {
        int r = idx >> 5, c = idx & 31;
        float4 t = *(const float4*)(X + (size_t)(row0 + r)*DIM + c*4);
        __half2* d = (__half2*)(sA + r*LDH + c*4);
        d[0] = __floats2half2_rn(t.x, t.y);
        d[1] = __floats2half2_rn(t.z, t.w);
    }
    // stage W (fp32 -> fp16), full 128x128
    for (int idx = tid; idx < 128*32; idx += 256) {
        int r = idx >> 5, c = idx & 31;
        float4 t = *(const float4*)(Wm + (size_t)r*DIM + c*4);
        __half2* d = (__half2*)(sB + r*LDH + c*4);
        d[0] = __floats2half2_rn(t.x, t.y);
        d[1] = __floats2half2_rn(t.z, t.w);
    }
    __syncthreads();

    wmma::fragment<wmma::accumulator,16,16,16,float> acc[2][2];
    #pragma unroll
    for (int i = 0; i < 2; i++)
        #pragma unroll
        for (int j = 0; j < 2; j++) wmma::fill_fragment(acc[i][j], 0.0f);

    #pragma unroll
    for (int k = 0; k < 8; k++) {
        wmma::fragment<wmma::matrix_a,16,16,16,__half,wmma::row_major> fa[2];
        wmma::fragment<wmma::matrix_b,16,16,16,__half,wmma::row_major> fb[2];
        #pragma unroll
        for (int i = 0; i < 2; i++)
            wmma::load_matrix_sync(fa[i], sA + (wr*32 + i*16)*LDH + k*16, LDH);
        #pragma unroll
        for (int j = 0; j < 2; j++)
            wmma::load_matrix_sync(fb[j], sB + (k*16)*LDH + wc*32 + j*16, LDH);
        #pragma unroll
        for (int i = 0; i < 2; i++)
            #pragma unroll
            for (int j = 0; j < 2; j++)
                wmma::mma_sync(acc[i][j], fa[i], fb[j], acc[i][j]);
    }
    __syncthreads();   // done reading sB before aliasing as sO
    #pragma unroll
    for (int i = 0; i < 2; i++)
        #pragma unroll
        for (int j = 0; j < 2; j++)
            wmma::store_matrix_sync(sO + (wr*32 + i*16)*LDS4 + wc*32 + j*16,
                                    acc[i][j], LDS4, wmma::mem_row_major);
    __syncthreads();
    for (int idx = tid; idx < 64*128; idx += 256) {
        int r = idx >> 7, e = idx & 127;
        outp[(size_t)(row0 + r)*DIM + e] = __float2half_rn(sO[r*LDS4 + e] + bm[e]);
    }
}

// ============================================================
// K3 (FUSED, fp16 wmma): per (b,h,128-row tile):
//   S = Q K^T (fp32 acc) ; P = fp16(exp(S*SCALE*adj)) ; O += P V ; O/l -> g_ocat
// grid (16,16), 256 threads (8 warps, each a 16x128 strip)
// smem: Q 34816 | K 34816 | V 34816 | P 34816 | S 67584  = 206848 B
// ============================================================
__global__ __launch_bounds__(256, 1) void fused_attn_fp16() {
    extern __shared__ __align__(16) char dsm[];
    __half* sQ = (__half*)dsm;
    __half* sK = (__half*)(dsm + 34816);
    __half* sV = (__half*)(dsm + 2*34816);
    __half* sP = (__half*)(dsm + 3*34816);
    float*  sS = (float*)(dsm + 4*34816);
    __shared__ float sL[128][2];

    const int tid  = threadIdx.x;
    const int warp = tid >> 5;
    const int n0 = blockIdx.x * 128;
    const int b = blockIdx.y >> 3, h = blockIdx.y & 7;

    const __half* qp  = g_q + (size_t)h*BN_*DIM + (size_t)b*NTOK*DIM;
    const __half* kp  = g_k + (size_t)h*BN_*DIM + (size_t)b*NTOK*DIM;
    const __half* vp  = g_v + (size_t)h*BN_*DIM + (size_t)b*NTOK*DIM;
    const float* adjp = g_adjsum + (size_t)b*NTOK*NTOK;

    // ---- stage Q (raw fp16 copy, 128 rows x 16 uint4) ----
    for (int idx = tid; idx < 128*16; idx += 256) {
        int r = idx >> 4, c = idx & 15;
        *(uint4*)(sQ + r*LDH + c*8) = *(const uint4*)(qp + (size_t)(n0 + r)*DIM + c*8);
    }
    __syncthreads();

    wmma::fragment<wmma::accumulator,16,16,16,float> oacc[8];
    #pragma unroll
    for (int j = 0; j < 8; j++) wmma::fill_fragment(oacc[j], 0.0f);

    const int row  = tid >> 1;          // 0..127 (exp/epilogue row)
    const int half = tid & 1;           // 64-col half
    float lacc = 0.f;

    for (int it = 0; it < 16; it++) {
        const int m0 = it * 128;
        // ---- copy K,V tiles (raw fp16) ----
        for (int idx = tid; idx < 128*16; idx += 256) {
            int r = idx >> 4, c = idx & 15;
            *(uint4*)(sK + r*LDH + c*8) = *(const uint4*)(kp + (size_t)(m0 + r)*DIM + c*8);
            *(uint4*)(sV + r*LDH + c*8) = *(const uint4*)(vp + (size_t)(m0 + r)*DIM + c*8);
        }
        __syncthreads();

        // ---- S = Q K^T : warp computes 16x128 strip ----
        {
            wmma::fragment<wmma::accumulator,16,16,16,float> sacc[8];
            #pragma unroll
            for (int j = 0; j < 8; j++) wmma::fill_fragment(sacc[j], 0.0f);
            #pragma unroll
            for (int k = 0; k < 8; k++) {
                wmma::fragment<wmma::matrix_a,16,16,16,__half,wmma::row_major> aQ;
                wmma::load_matrix_sync(aQ, sQ + (warp*16)*LDH + k*16, LDH);
                #pragma unroll
                for (int j = 0; j < 8; j++) {
                    wmma::fragment<wmma::matrix_b,16,16,16,__half,wmma::col_major> bK;
                    wmma::load_matrix_sync(bK, sK + (j*16)*LDH + k*16, LDH);
                    wmma::mma_sync(sacc[j], aQ, bK, sacc[j]);
                }
            }
            #pragma unroll
            for (int j = 0; j < 8; j++)
                wmma::store_matrix_sync(sS + (warp*16)*LDS4 + j*16, sacc[j],
                                        LDS4, wmma::mem_row_major);
        }
        __syncthreads();

        // ---- P = exp(S*SCALE*adj) -> fp16, accumulate row-sum ----
        {
            const float* srow = sS + row*LDS4 + half*64;
            const float* arow = adjp + (size_t)(n0 + row)*NTOK + m0 + half*64;
            __half2* prow = (__half2*)(sP + row*LDH + half*64);
            float lsum = 0.f;
            #pragma unroll
            for (int c = 0; c < 64; c += 4) {
                float4 a4 = *(const float4*)(arow + c);
                float e0 = __expf(srow[c+0] * SCALE * a4.x);
                float e1 = __expf(srow[c+1] * SCALE * a4.y);
                float e2 = __expf(srow[c+2] * SCALE * a4.z);
                float e3 = __expf(srow[c+3] * SCALE * a4.w);
                lsum += (e0 + e1) + (e2 + e3);
                prow[c/2]     = __floats2half2_rn(e0, e1);
                prow[c/2 + 1] = __floats2half2_rn(e2, e3);
            }
            lacc += lsum;
        }
        __syncthreads();

        // ---- O += P @ V ----
        #pragma unroll
        for (int k = 0; k < 8; k++) {
            wmma::fragment<wmma::matrix_a,16,16,16,__half,wmma::row_major> aP;
            wmma::load_matrix_sync(aP, sP + (warp*16)*LDH + k*16, LDH);
            #pragma unroll
            for (int j = 0; j < 8; j++) {
                wmma::fragment<wmma::matrix_b,16,16,16,__half,wmma::row_major> bV;
                wmma::load_matrix_sync(bV, sV + (k*16)*LDH + j*16, LDH);
                wmma::mma_sync(oacc[j], aP, bV, oacc[j]);
            }
        }
        __syncthreads();   // before next iter overwrites sK/sV/sP (and sS)
    }

    // ---- epilogue: O / l -> g_ocat (fp16) ----
    sL[row][half] = lacc;
    #pragma unroll
    for (int j = 0; j < 8; j++)
        wmma::store_matrix_sync(sS + (warp*16)*LDS4 + j*16, oacc[j],
                                LDS4, wmma::mem_row_major);
    __syncthreads();
    {
        const float linv = 1.0f / (sL[row][0] + sL[row][1]);
        const float* orow = sS + row*LDS4 + half*64;
        __half2* drow = (__half2*)(g_ocat + (size_t)(b*NTOK + n0 + row)*FEAT
                                   + h*DIM + half*64);
        #pragma unroll
        for (int c = 0; c < 32; c++)
            drow[c] = __floats2half2_rn(orow[2*c] * linv, orow[2*c+1] * linv);
    }
}

// ============================================================
// K4a: outproj split-K partial (fp16 wmma)
// grid (64, 4, 4), block 128 (4 warps 2x2, each 32x32)
// ============================================================
__global__ void outproj_part(const float* __restrict__ Wout) {
    __shared__ __align__(16) char smem_raw[18432];
    __half* sA = (__half*)smem_raw;                 // 64 x 72
    __half* sB = (__half*)(smem_raw + 64*72*2);     // 64 x 72
    float*  sO = (float*)smem_raw;                  // 64 x 68 (alias, after MMA)
    const int tid  = threadIdx.x;
    const int warp = tid >> 5;
    const int wr = warp >> 1, wc = warp & 1;
    const int r0 = blockIdx.x * 64, c0 = blockIdx.y * 64;
    const int k0 = blockIdx.z * 256;
    float* psum = g_psum[blockIdx.z];

    wmma::fragment<wmma::accumulator,16,16,16,float> acc[2][2];
    #pragma unroll
    for (int i = 0; i < 2; i++)
        #pragma unroll
        for (int j = 0; j < 2; j++) wmma::fill_fragment(acc[i][j], 0.0f);

    for (int kb = 0; kb < 256; kb += 64) {
        // sA: ocat fp16 raw copy (64 rows x 8 uint4)
        for (int idx = tid; idx < 64*8; idx += 128) {
            int r = idx >> 3, c = idx & 7;
            *(uint4*)(sA + r*72 + c*8) =
                *(const uint4*)(g_ocat + (size_t)(r0 + r)*FEAT + k0 + kb + c*8);
        }
        // sB: Wout fp32 -> fp16 (64 k-rows x 64 cols)
        for (int idx = tid; idx < 64*16; idx += 128) {
            int r = idx >> 4, c = idx & 15;
            float4 t = *(const float4*)(Wout + (size_t)(k0 + kb + r)*DOUT + c0 + c*4);
            __half2* d = (__half2*)(sB + r*72 + c*4);
            d[0] = __floats2half2_rn(t.x, t.y);
            d[1] = __floats2half2_rn(t.z, t.w);
        }
        __syncthreads();
        #pragma unroll
        for (int kk = 0; kk < 4; kk++) {
            wmma::fragment<wmma::matrix_a,16,16,16,__half,wmma::row_major> fa[2];
            wmma::fragment<wmma::matrix_b,16,16,16,__half,wmma::row_major> fb[2];
            #pragma unroll
            for (int i = 0; i < 2; i++)
                wmma::load_matrix_sync(fa[i], sA + (wr*32 + i*16)*72 + kk*16, 72);
            #pragma unroll
            for (int j = 0; j < 2; j++)
                wmma::load_matrix_sync(fb[j], sB + (kk*16)*72 + wc*32 + j*16, 72);
            #pragma unroll
            for (int i = 0; i < 2; i++)
                #pragma unroll
                for (int j = 0; j < 2; j++)
                    wmma::mma_sync(acc[i][j], fa[i], fb[j], acc[i][j]);
        }
        __syncthreads();
    }
    #pragma unroll
    for (int i = 0; i < 2; i++)
        #pragma unroll
        for (int j = 0; j < 2; j++)
            wmma::store_matrix_sync(sO + (wr*32 + i*16)*68 + wc*32 + j*16,
                                    acc[i][j], 68, wmma::mem_row_major);
    __syncthreads();
    for (int idx = tid; idx < 64*64; idx += 128) {
        int r = idx >> 6, c = idx & 63;
        psum[(size_t)(r0 + r)*DOUT + c0 + c] = sO[r*68 + c];
    }
}

// ============================================================
// K4b: out = sum_z psum[z] + bout
// ============================================================
__global__ void outproj_reduce(const float* __restrict__ bout,
                               float* __restrict__ out) {
    size_t i = (size_t)blockIdx.x * blockDim.x + threadIdx.x;
    if (i < (size_t)BN_*DOUT) {
        float s = g_psum[0][i] + g_psum[1][i] + g_psum[2][i] + g_psum[3][i];
        out[i] = s + bout[i & (DOUT - 1)];
    }
}

// ============================================================
extern "C" void kernel_launch(void* const* d_in, const int* in_sizes, int n_in,
                              void* d_out, int out_size) {
    const float* X    = (const float*)d_in[0];
    const float* adj  = (const float*)d_in[1];
    const float* Wq   = (const float*)d_in[2];
    const float* bq   = (const float*)d_in[3];
    const float* Wk   = (const float*)d_in[4];
    const float* bk   = (const float*)d_in[5];
    const float* Wv   = (const float*)d_in[6];
    const float* bv   = (const float*)d_in[7];
    const float* Wout = (const float*)d_in[8];
    const float* bout = (const float*)d_in[9];
    float* out = (float*)d_out;

    const int fused_smem = 4*34816 + 67584;   // 206,848 B
    cudaFuncSetAttribute(fused_attn_fp16,
                         cudaFuncAttributeMaxDynamicSharedMemorySize, fused_smem);

    {
        size_t total = (size_t)BB*NTOK*NTOK;
        adjsum_kernel<<<(unsigned)((total + 255) / 256), 256>>>((const float4*)adj);
    }
    qkv_kernel<<<dim3(BN_/64, 3*NH), 256>>>(X, Wq, bq, Wk, bk, Wv, bv);
    fused_attn_fp16<<<dim3(NTOK/128, BB*NH), 256, fused_smem>>>();
    outproj_part<<<dim3(BN_/64, DOUT/64, 4), 128>>>(Wout);
    {
        size_t total = (size_t)BN_*DOUT;
        outproj_reduce<<<(unsigned)((total + 255) / 256), 256>>>(bout, out);
    }
}